// round 3
// baseline (speedup 1.0000x reference)
#include <cuda_runtime.h>
#include <cuda_bf16.h>
#include <cstdint>

#define N_NODES 100000
#define N_EDGES 800000
#define F 128
#define C 64

// Scratch (static device globals — no runtime allocation allowed)
__device__ float g_y[(size_t)N_NODES * C];      // y = x @ W^T
__device__ float g_accum[(size_t)N_NODES * C];  // y[v] + sum_{u->v} y[u]
__device__ float g_deg[N_NODES];                // 1 + in_degree
__device__ int   g_is64;                        // edge index dtype flag

// Packed-pair fp32 FMA (sm_103a f32x2 pipe — 2 FMAs per FMA-pipe slot)
#define FMA_F32X2(d, a, b, c) \
    asm("fma.rn.f32x2 %0, %1, %2, %3;" : "=l"(d) : "l"(a), "l"(b), "l"(c))
#define PACK_F32X2(out, lo, hi) \
    asm("mov.b64 %0, {%1, %2};" : "=l"(out) : "f"(lo), "f"(hi))
#define UNPACK_F32X2(lo, hi, in) \
    asm("mov.b64 {%0, %1}, %2;" : "=f"(lo), "=f"(hi) : "l"(in))

// ---------------------------------------------------------------------------
// Probe: are edge indices int64 or int32? Values are < 100000, so if int64,
// every odd 32-bit word of the first 256 entries is zero.
// ---------------------------------------------------------------------------
__global__ void detect_kernel(const unsigned int* __restrict__ p) {
    if (threadIdx.x == 0 && blockIdx.x == 0) {
        int all0 = 1;
        for (int i = 0; i < 256; i++) {
            if (p[2 * i + 1] != 0u) { all0 = 0; break; }
        }
        g_is64 = all0;
    }
}

// ---------------------------------------------------------------------------
// Kernel 1: y = x @ W^T using packed f32x2 FMAs.
// Smem holds W re-packed as [k][c_pair]: Wp[k*32 + c2] = (W[2c2][k], W[2c2+1][k])
// (64-bit packed pair). One thread = one node; 32 packed accumulators.
// Also seeds accum = y (self term) and deg = 1 (the +1).
// ---------------------------------------------------------------------------
__global__ void __launch_bounds__(128) gemm_kernel(const float* __restrict__ x,
                                                   const float* __restrict__ W) {
    __shared__ unsigned long long Wp[F * (C / 2)];  // 128*32*8B = 32KB
    const int tid = threadIdx.x;

    // Stage + transpose + pair-pack W (one-time, 8K scalar loads per block)
    for (int i = tid; i < F * (C / 2); i += blockDim.x) {
        int k  = i / (C / 2);
        int c2 = i % (C / 2);
        float lo = W[(2 * c2) * F + k];
        float hi = W[(2 * c2 + 1) * F + k];
        unsigned long long p;
        PACK_F32X2(p, lo, hi);
        Wp[k * (C / 2) + c2] = p;
    }
    __syncthreads();

    const int node = blockIdx.x * blockDim.x + tid;
    if (node >= N_NODES) return;

    unsigned long long acc2[C / 2];
#pragma unroll
    for (int i = 0; i < C / 2; i++) acc2[i] = 0ull;  // (0.0f, 0.0f)

    const float4* x4 = reinterpret_cast<const float4*>(x + (size_t)node * F);

#pragma unroll 1
    for (int k4 = 0; k4 < F / 4; k4++) {
        float4 xv = x4[k4];
        float xs[4] = {xv.x, xv.y, xv.z, xv.w};
#pragma unroll
        for (int j = 0; j < 4; j++) {
            const int k = 4 * k4 + j;
            unsigned long long x2;
            PACK_F32X2(x2, xs[j], xs[j]);
            const ulonglong2* row =
                reinterpret_cast<const ulonglong2*>(Wp + k * (C / 2));
#pragma unroll
            for (int c4 = 0; c4 < C / 4; c4++) {  // 16 LDS.128 -> 32 FFMA2
                ulonglong2 w = row[c4];
                FMA_F32X2(acc2[2 * c4],     x2, w.x, acc2[2 * c4]);
                FMA_F32X2(acc2[2 * c4 + 1], x2, w.y, acc2[2 * c4 + 1]);
            }
        }
    }

    float4* y4 = reinterpret_cast<float4*>(g_y     + (size_t)node * C);
    float4* a4 = reinterpret_cast<float4*>(g_accum + (size_t)node * C);
#pragma unroll
    for (int c4 = 0; c4 < C / 4; c4++) {
        float4 v;
        UNPACK_F32X2(v.x, v.y, acc2[2 * c4]);
        UNPACK_F32X2(v.z, v.w, acc2[2 * c4 + 1]);
        y4[c4] = v;
        a4[c4] = v;
    }
    g_deg[node] = 1.0f;
}

// ---------------------------------------------------------------------------
// Kernel 2: edge scatter. 16 lanes per edge; each lane gathers one float4 of
// y[src] (L2-resident) and issues a vector reduction into accum[dst].
// ---------------------------------------------------------------------------
__global__ void __launch_bounds__(256) edge_kernel(const void* __restrict__ src_p,
                                                   const void* __restrict__ dst_p) {
    const int e    = blockIdx.x * (blockDim.x / 16) + (threadIdx.x >> 4);
    const int lane = threadIdx.x & 15;
    if (e >= N_EDGES) return;

    const int is64 = g_is64;  // uniform load
    long long s, d;
    if (is64) {
        s = reinterpret_cast<const long long*>(src_p)[e];
        d = reinterpret_cast<const long long*>(dst_p)[e];
    } else {
        s = reinterpret_cast<const int*>(src_p)[e];
        d = reinterpret_cast<const int*>(dst_p)[e];
    }

    const float4* ys = reinterpret_cast<const float4*>(g_y + (size_t)s * C);
    float4 v = ys[lane];

    float* ap = g_accum + (size_t)d * C + lane * 4;
    asm volatile("red.global.add.v4.f32 [%0], {%1, %2, %3, %4};"
                 :: "l"(ap), "f"(v.x), "f"(v.y), "f"(v.z), "f"(v.w)
                 : "memory");

    if (lane == 0) atomicAdd(g_deg + d, 1.0f);
}

// ---------------------------------------------------------------------------
// Kernel 3: out = accum / deg + b. Streaming, float4 per thread.
// ---------------------------------------------------------------------------
__global__ void __launch_bounds__(256) final_kernel(const float* __restrict__ b,
                                                    float* __restrict__ out) {
    const int i = blockIdx.x * blockDim.x + threadIdx.x;  // float4 index
    if (i >= (N_NODES * C) / 4) return;

    const int node = i / (C / 4);
    const int c4   = i % (C / 4);

    float4 a    = reinterpret_cast<const float4*>(g_accum)[i];
    float  dinv = 1.0f / g_deg[node];
    float4 bv   = reinterpret_cast<const float4*>(b)[c4];

    float4 o;
    o.x = a.x * dinv + bv.x;
    o.y = a.y * dinv + bv.y;
    o.z = a.z * dinv + bv.z;
    o.w = a.w * dinv + bv.w;
    reinterpret_cast<float4*>(out)[i] = o;
}

// ---------------------------------------------------------------------------
// Launcher. Inputs (metadata order): x, edge_src, edge_dst, W_neigh, b_neigh.
// ---------------------------------------------------------------------------
extern "C" void kernel_launch(void* const* d_in, const int* in_sizes, int n_in,
                              void* d_out, int out_size) {
    const float* x   = (const float*)d_in[0];
    const void*  es  = d_in[1];
    const void*  ed  = d_in[2];
    const float* W   = (const float*)d_in[3];
    const float* b   = (const float*)d_in[4];
    float*       out = (float*)d_out;

    detect_kernel<<<1, 32>>>((const unsigned int*)es);

    {
        const int threads = 128;
        const int blocks  = (N_NODES + threads - 1) / threads;
        gemm_kernel<<<blocks, threads>>>(x, W);
    }
    {
        const int threads = 256;
        const int edges_per_block = threads / 16;
        const int blocks = (N_EDGES + edges_per_block - 1) / edges_per_block;
        edge_kernel<<<blocks, threads>>>(es, ed);
    }
    {
        const int total4  = (N_NODES * C) / 4;
        const int threads = 256;
        const int blocks  = (total4 + threads - 1) / threads;
        final_kernel<<<blocks, threads>>>(b, out);
    }
}

// round 8
// speedup vs baseline: 1.3283x; 1.3283x over previous
#include <cuda_runtime.h>
#include <cuda_bf16.h>
#include <cstdint>

#define N_NODES 100000
#define N_EDGES 800000
#define F 128
#define C 64

#define SCAN_BLK 256
#define NBLK_SCAN ((N_NODES + SCAN_BLK - 1) / SCAN_BLK)  // 391

// Scratch (static device globals — no runtime allocation allowed)
__device__ float g_y[(size_t)N_NODES * C];  // y = x @ W^T
__device__ int   g_cnt[N_NODES];            // in-degree
__device__ int   g_start[N_NODES];          // CSR offsets (exclusive scan)
__device__ int   g_cursor[N_NODES];         // scatter cursors
__device__ int   g_bsum[NBLK_SCAN];         // scan block partials
__device__ int   g_elist[N_EDGES];          // CSR src lists
__device__ int   g_is64;                    // edge index dtype flag

// ---------------------------------------------------------------------------
// Probe: int64 vs int32 edge indices (values < 100000 -> odd words zero if 64)
// ---------------------------------------------------------------------------
__global__ void detect_kernel(const unsigned int* __restrict__ p) {
    if (threadIdx.x == 0 && blockIdx.x == 0) {
        int all0 = 1;
        for (int i = 0; i < 256; i++) {
            if (p[2 * i + 1] != 0u) { all0 = 0; break; }
        }
        g_is64 = all0;
    }
}

__device__ __forceinline__ long long load_idx(const void* p, int e, int is64) {
    return is64 ? reinterpret_cast<const long long*>(p)[e]
                : (long long)reinterpret_cast<const int*>(p)[e];
}

// ---------------------------------------------------------------------------
// Kernel 1: y = x @ W^T. W (64x128 fp32 = 32KB) in smem, 1 thread = 1 node,
// 64 fp32 accumulators, float4 loads. Also zeroes the degree counters.
// ---------------------------------------------------------------------------
__global__ void __launch_bounds__(128) gemm_kernel(const float* __restrict__ x,
                                                   const float* __restrict__ W) {
    __shared__ float Ws[C * F];
    const int tid = threadIdx.x;

    const float4* W4  = reinterpret_cast<const float4*>(W);
    float4*       Ws4 = reinterpret_cast<float4*>(Ws);
    for (int i = tid; i < (C * F) / 4; i += blockDim.x) Ws4[i] = W4[i];
    __syncthreads();

    const int node = blockIdx.x * blockDim.x + tid;
    if (node >= N_NODES) return;

    g_cnt[node] = 0;

    float acc[C];
#pragma unroll
    for (int c = 0; c < C; c++) acc[c] = 0.0f;

    const float4* x4 = reinterpret_cast<const float4*>(x + (size_t)node * F);

#pragma unroll 1
    for (int k = 0; k < F / 4; k++) {
        float4 xv = x4[k];
#pragma unroll
        for (int c = 0; c < C; c++) {
            float4 wv = Ws4[c * (F / 4) + k];
            acc[c] += xv.x * wv.x;
            acc[c] += xv.y * wv.y;
            acc[c] += xv.z * wv.z;
            acc[c] += xv.w * wv.w;
        }
    }

    float4* y4 = reinterpret_cast<float4*>(g_y + (size_t)node * C);
#pragma unroll
    for (int c4 = 0; c4 < C / 4; c4++) {
        y4[c4] = make_float4(acc[4 * c4], acc[4 * c4 + 1],
                             acc[4 * c4 + 2], acc[4 * c4 + 3]);
    }
}

// ---------------------------------------------------------------------------
// Kernel 2: in-degree histogram (spread int atomics)
// ---------------------------------------------------------------------------
__global__ void __launch_bounds__(256) hist_kernel(const void* __restrict__ dst_p) {
    const int e = blockIdx.x * blockDim.x + threadIdx.x;
    if (e >= N_EDGES) return;
    const int d = (int)load_idx(dst_p, e, g_is64);
    atomicAdd(&g_cnt[d], 1);
}

// ---------------------------------------------------------------------------
// Kernels 3a/3b/3c: exclusive prefix scan of g_cnt -> g_start (two-level)
// ---------------------------------------------------------------------------
__global__ void __launch_bounds__(SCAN_BLK) scan1_kernel() {
    __shared__ int sh[SCAN_BLK];
    const int tid = threadIdx.x;
    const int i   = blockIdx.x * SCAN_BLK + tid;
    const int v   = (i < N_NODES) ? g_cnt[i] : 0;
    sh[tid] = v;
    __syncthreads();
#pragma unroll
    for (int off = 1; off < SCAN_BLK; off <<= 1) {
        int t = (tid >= off) ? sh[tid - off] : 0;
        __syncthreads();
        sh[tid] += t;
        __syncthreads();
    }
    const int incl = sh[tid];
    if (i < N_NODES) g_start[i] = incl - v;          // block-local exclusive
    if (tid == SCAN_BLK - 1) g_bsum[blockIdx.x] = incl;
}

__global__ void __launch_bounds__(512) scan2_kernel() {
    __shared__ int sh[512];
    const int tid = threadIdx.x;
    const int v   = (tid < NBLK_SCAN) ? g_bsum[tid] : 0;
    sh[tid] = v;
    __syncthreads();
#pragma unroll
    for (int off = 1; off < 512; off <<= 1) {
        int t = (tid >= off) ? sh[tid - off] : 0;
        __syncthreads();
        sh[tid] += t;
        __syncthreads();
    }
    if (tid < NBLK_SCAN) g_bsum[tid] = sh[tid] - v;  // exclusive
}

__global__ void __launch_bounds__(SCAN_BLK) scan3_kernel() {
    const int i = blockIdx.x * SCAN_BLK + threadIdx.x;
    if (i >= N_NODES) return;
    const int s = g_start[i] + g_bsum[blockIdx.x];
    g_start[i]  = s;
    g_cursor[i] = s;
}

// ---------------------------------------------------------------------------
// Kernel 4: scatter src ids into CSR lists
// ---------------------------------------------------------------------------
__global__ void __launch_bounds__(256) scatter_kernel(const void* __restrict__ src_p,
                                                      const void* __restrict__ dst_p) {
    const int e = blockIdx.x * blockDim.x + threadIdx.x;
    if (e >= N_EDGES) return;
    const int is64 = g_is64;
    const int s = (int)load_idx(src_p, e, is64);
    const int d = (int)load_idx(dst_p, e, is64);
    const int pos = atomicAdd(&g_cursor[d], 1);
    g_elist[pos] = s;
}

// ---------------------------------------------------------------------------
// Kernel 5: gather + finalize. 16 lanes per dst node; lane owns one float4
// channel slice. out[v] = (y[v] + sum_u y[u]) / (deg+1) + b.
// ---------------------------------------------------------------------------
__global__ void __launch_bounds__(256) gather_kernel(const float* __restrict__ b,
                                                     float* __restrict__ out) {
    const int v    = blockIdx.x * (blockDim.x / 16) + (threadIdx.x >> 4);
    const int lane = threadIdx.x & 15;
    if (v >= N_NODES) return;

    const int start = g_start[v];
    const int cnt   = g_cnt[v];

    float4 acc = reinterpret_cast<const float4*>(g_y + (size_t)v * C)[lane];

    if (cnt > 0) {
        int s = g_elist[start];
        float4 u = reinterpret_cast<const float4*>(g_y + (size_t)s * C)[lane];
        for (int i = 1; i < cnt; i++) {
            int s_n = g_elist[start + i];
            float4 u_n = reinterpret_cast<const float4*>(g_y + (size_t)s_n * C)[lane];
            acc.x += u.x; acc.y += u.y; acc.z += u.z; acc.w += u.w;
            u = u_n;
        }
        acc.x += u.x; acc.y += u.y; acc.z += u.z; acc.w += u.w;
    }

    const float inv = 1.0f / (float)(cnt + 1);
    const float4 bv = reinterpret_cast<const float4*>(b)[lane];
    float4 o;
    o.x = acc.x * inv + bv.x;
    o.y = acc.y * inv + bv.y;
    o.z = acc.z * inv + bv.z;
    o.w = acc.w * inv + bv.w;
    reinterpret_cast<float4*>(out)[(size_t)v * (C / 4) + lane] = o;
}

// ---------------------------------------------------------------------------
// Launcher. Inputs (metadata order): x, edge_src, edge_dst, W_neigh, b_neigh.
// ---------------------------------------------------------------------------
extern "C" void kernel_launch(void* const* d_in, const int* in_sizes, int n_in,
                              void* d_out, int out_size) {
    const float* x   = (const float*)d_in[0];
    const void*  es  = d_in[1];
    const void*  ed  = d_in[2];
    const float* W   = (const float*)d_in[3];
    const float* b   = (const float*)d_in[4];
    float*       out = (float*)d_out;

    detect_kernel<<<1, 32>>>((const unsigned int*)es);

    gemm_kernel<<<(N_NODES + 127) / 128, 128>>>(x, W);

    hist_kernel<<<(N_EDGES + 255) / 256, 256>>>(ed);

    scan1_kernel<<<NBLK_SCAN, SCAN_BLK>>>();
    scan2_kernel<<<1, 512>>>();
    scan3_kernel<<<NBLK_SCAN, SCAN_BLK>>>();

    scatter_kernel<<<(N_EDGES + 255) / 256, 256>>>(es, ed);

    gather_kernel<<<(N_NODES * 16 + 255) / 256, 256>>>(b, out);
}

// round 13
// speedup vs baseline: 1.7011x; 1.2806x over previous
#include <cuda_runtime.h>
#include <cuda_bf16.h>
#include <mma.h>
#include <cstdint>

using namespace nvcuda;

#define N_NODES 100000
#define N_EDGES 800000
#define F 128
#define C 64

#define TILE_M 128
#define N_TILES ((N_NODES + TILE_M - 1) / TILE_M)  // 782
#define N_PAD   (N_TILES * TILE_M)                 // 100096

#define SCAN_BLK 256
#define NBLK_SCAN ((N_NODES + SCAN_BLK - 1) / SCAN_BLK)  // 391

// Scratch (static device globals — no runtime allocation allowed)
__device__ float g_y[(size_t)N_PAD * C];    // y = x @ W^T (padded rows for ragged tile)
__device__ int   g_cnt[N_NODES];            // in-degree
__device__ int   g_start[N_NODES];          // CSR offsets (exclusive scan)
__device__ int   g_cursor[N_NODES];         // scatter cursors
__device__ int   g_bsum[NBLK_SCAN];         // scan block partials
__device__ int   g_elist[N_EDGES];          // CSR src lists
__device__ int   g_is64;                    // edge index dtype flag

// Smem tile layout for the wmma GEMM (bf16, padded leading dims)
#define LDA 136
#define LDB 136
#define A_BYTES (TILE_M * LDA * 2)          // 34816
#define B_BYTES (C * LDB * 2)               // 17408
#define OFF_AHI 0
#define OFF_ALO (A_BYTES)
#define OFF_BHI (2 * A_BYTES)
#define OFF_BLO (2 * A_BYTES + B_BYTES)
#define GEMM_SMEM (2 * A_BYTES + 2 * B_BYTES)  // 104448 bytes

// ---------------------------------------------------------------------------
// Probe: int64 vs int32 edge indices (parallel, warp-wide)
// ---------------------------------------------------------------------------
__global__ void detect_kernel(const unsigned int* __restrict__ p) {
    const int lid = threadIdx.x;
    unsigned int v = 0;
    for (int i = lid; i < 256; i += 32) v |= p[2 * i + 1];
    const unsigned int any = __ballot_sync(0xFFFFFFFFu, v != 0u);
    if (lid == 0) g_is64 = (any == 0u) ? 1 : 0;
}

__device__ __forceinline__ long long load_idx(const void* p, int e, int is64) {
    return is64 ? reinterpret_cast<const long long*>(p)[e]
                : (long long)reinterpret_cast<const int*>(p)[e];
}

// ---------------------------------------------------------------------------
// Kernel 1: y = x @ W^T via wmma bf16 with 3-product hi/lo split:
//   D = A_hi*B_hi + A_lo*B_hi + A_hi*B_lo  (fp32 accumulators)
// CTA: 128 threads (4 warps), tile M=128, N=64, K=128.
// Warp w computes rows [w*32, w*32+32). Also zeroes g_cnt.
// ---------------------------------------------------------------------------
__global__ void __launch_bounds__(128) gemm_wmma_kernel(const float* __restrict__ x,
                                                        const float* __restrict__ W) {
    extern __shared__ char smem[];
    __nv_bfloat16* Ahi = reinterpret_cast<__nv_bfloat16*>(smem + OFF_AHI);
    __nv_bfloat16* Alo = reinterpret_cast<__nv_bfloat16*>(smem + OFF_ALO);
    __nv_bfloat16* Bhi = reinterpret_cast<__nv_bfloat16*>(smem + OFF_BHI);
    __nv_bfloat16* Blo = reinterpret_cast<__nv_bfloat16*>(smem + OFF_BLO);

    const int tid  = threadIdx.x;
    const int wid  = tid >> 5;
    const int row0 = blockIdx.x * TILE_M;

    // ---- Load + convert A tile (x rows -> bf16 hi/lo), coalesced float4 ----
    {
        const float4* x4 = reinterpret_cast<const float4*>(x);
        for (int i = tid; i < (TILE_M * F) / 4; i += 128) {
            const int row = i >> 5;           // 32 float4 per row
            const int col = (i & 31) << 2;
            const int gr  = row0 + row;
            float4 v = (gr < N_NODES) ? x4[(size_t)gr * (F / 4) + (i & 31)]
                                      : make_float4(0.f, 0.f, 0.f, 0.f);
            __nv_bfloat16 h0 = __float2bfloat16(v.x);
            __nv_bfloat16 h1 = __float2bfloat16(v.y);
            __nv_bfloat16 h2 = __float2bfloat16(v.z);
            __nv_bfloat16 h3 = __float2bfloat16(v.w);
            __nv_bfloat16 l0 = __float2bfloat16(v.x - __bfloat162float(h0));
            __nv_bfloat16 l1 = __float2bfloat16(v.y - __bfloat162float(h1));
            __nv_bfloat16 l2 = __float2bfloat16(v.z - __bfloat162float(h2));
            __nv_bfloat16 l3 = __float2bfloat16(v.w - __bfloat162float(h3));
            __nv_bfloat162* hp =
                reinterpret_cast<__nv_bfloat162*>(Ahi + row * LDA + col);
            hp[0] = __nv_bfloat162(h0, h1);
            hp[1] = __nv_bfloat162(h2, h3);
            __nv_bfloat162* lp =
                reinterpret_cast<__nv_bfloat162*>(Alo + row * LDA + col);
            lp[0] = __nv_bfloat162(l0, l1);
            lp[1] = __nv_bfloat162(l2, l3);
        }
    }
    // ---- Load + convert B tile (W [c][k] -> bf16 hi/lo) ----
    {
        const float4* w4 = reinterpret_cast<const float4*>(W);
        for (int i = tid; i < (C * F) / 4; i += 128) {
            const int row = i >> 5;
            const int col = (i & 31) << 2;
            float4 v = w4[i];
            __nv_bfloat16 h0 = __float2bfloat16(v.x);
            __nv_bfloat16 h1 = __float2bfloat16(v.y);
            __nv_bfloat16 h2 = __float2bfloat16(v.z);
            __nv_bfloat16 h3 = __float2bfloat16(v.w);
            __nv_bfloat16 l0 = __float2bfloat16(v.x - __bfloat162float(h0));
            __nv_bfloat16 l1 = __float2bfloat16(v.y - __bfloat162float(h1));
            __nv_bfloat16 l2 = __float2bfloat16(v.z - __bfloat162float(h2));
            __nv_bfloat16 l3 = __float2bfloat16(v.w - __bfloat162float(h3));
            __nv_bfloat162* hp =
                reinterpret_cast<__nv_bfloat162*>(Bhi + row * LDB + col);
            hp[0] = __nv_bfloat162(h0, h1);
            hp[1] = __nv_bfloat162(h2, h3);
            __nv_bfloat162* lp =
                reinterpret_cast<__nv_bfloat162*>(Blo + row * LDB + col);
            lp[0] = __nv_bfloat162(l0, l1);
            lp[1] = __nv_bfloat162(l2, l3);
        }
    }
    // zero degree counters while we're here
    if (row0 + tid < N_NODES) g_cnt[row0 + tid] = 0;
    __syncthreads();

    // ---- wmma mainloop: 3 products x 8 K-steps; warp owns 32 rows x 64 cols ----
    wmma::fragment<wmma::accumulator, 16, 16, 16, float> acc[2][4];
#pragma unroll
    for (int m = 0; m < 2; m++)
#pragma unroll
        for (int n = 0; n < 4; n++) wmma::fill_fragment(acc[m][n], 0.0f);

#pragma unroll
    for (int p = 0; p < 3; p++) {
        const __nv_bfloat16* Ap = (p == 1) ? Alo : Ahi;
        const __nv_bfloat16* Bp = (p == 2) ? Blo : Bhi;
#pragma unroll
        for (int k = 0; k < 8; k++) {
            wmma::fragment<wmma::matrix_a, 16, 16, 16, __nv_bfloat16,
                           wmma::row_major> fa[2];
            wmma::load_matrix_sync(fa[0], Ap + (wid * 32) * LDA + k * 16, LDA);
            wmma::load_matrix_sync(fa[1], Ap + (wid * 32 + 16) * LDA + k * 16, LDA);
#pragma unroll
            for (int n = 0; n < 4; n++) {
                wmma::fragment<wmma::matrix_b, 16, 16, 16, __nv_bfloat16,
                               wmma::col_major> fb;
                // element (k', c') = Bp[(n*16+c')*LDB + k*16+k'] = W[c][k]
                wmma::load_matrix_sync(fb, Bp + (n * 16) * LDB + k * 16, LDB);
                wmma::mma_sync(acc[0][n], fa[0], fb, acc[0][n]);
                wmma::mma_sync(acc[1][n], fa[1], fb, acc[1][n]);
            }
        }
    }

    // ---- Store: direct to g_y (padded, so ragged tail writes are safe) ----
    float* yb = g_y + (size_t)(row0 + wid * 32) * C;
#pragma unroll
    for (int m = 0; m < 2; m++)
#pragma unroll
        for (int n = 0; n < 4; n++)
            wmma::store_matrix_sync(yb + (size_t)m * 16 * C + n * 16,
                                    acc[m][n], C, wmma::mem_row_major);
}

// ---------------------------------------------------------------------------
// Kernel 2: in-degree histogram (spread int atomics)
// ---------------------------------------------------------------------------
__global__ void __launch_bounds__(256) hist_kernel(const void* __restrict__ dst_p) {
    const int e = blockIdx.x * blockDim.x + threadIdx.x;
    if (e >= N_EDGES) return;
    const int d = (int)load_idx(dst_p, e, g_is64);
    atomicAdd(&g_cnt[d], 1);
}

// ---------------------------------------------------------------------------
// Kernels 3a/3b/3c: exclusive prefix scan of g_cnt -> g_start (two-level)
// ---------------------------------------------------------------------------
__global__ void __launch_bounds__(SCAN_BLK) scan1_kernel() {
    __shared__ int sh[SCAN_BLK];
    const int tid = threadIdx.x;
    const int i   = blockIdx.x * SCAN_BLK + tid;
    const int v   = (i < N_NODES) ? g_cnt[i] : 0;
    sh[tid] = v;
    __syncthreads();
#pragma unroll
    for (int off = 1; off < SCAN_BLK; off <<= 1) {
        int t = (tid >= off) ? sh[tid - off] : 0;
        __syncthreads();
        sh[tid] += t;
        __syncthreads();
    }
    const int incl = sh[tid];
    if (i < N_NODES) g_start[i] = incl - v;          // block-local exclusive
    if (tid == SCAN_BLK - 1) g_bsum[blockIdx.x] = incl;
}

__global__ void __launch_bounds__(512) scan2_kernel() {
    __shared__ int sh[512];
    const int tid = threadIdx.x;
    const int v   = (tid < NBLK_SCAN) ? g_bsum[tid] : 0;
    sh[tid] = v;
    __syncthreads();
#pragma unroll
    for (int off = 1; off < 512; off <<= 1) {
        int t = (tid >= off) ? sh[tid - off] : 0;
        __syncthreads();
        sh[tid] += t;
        __syncthreads();
    }
    if (tid < NBLK_SCAN) g_bsum[tid] = sh[tid] - v;  // exclusive
}

__global__ void __launch_bounds__(SCAN_BLK) scan3_kernel() {
    const int i = blockIdx.x * SCAN_BLK + threadIdx.x;
    if (i >= N_NODES) return;
    const int s = g_start[i] + g_bsum[blockIdx.x];
    g_start[i]  = s;
    g_cursor[i] = s;
}

// ---------------------------------------------------------------------------
// Kernel 4: scatter src ids into CSR lists
// ---------------------------------------------------------------------------
__global__ void __launch_bounds__(256) scatter_kernel(const void* __restrict__ src_p,
                                                      const void* __restrict__ dst_p) {
    const int e = blockIdx.x * blockDim.x + threadIdx.x;
    if (e >= N_EDGES) return;
    const int is64 = g_is64;
    const int s = (int)load_idx(src_p, e, is64);
    const int d = (int)load_idx(dst_p, e, is64);
    const int pos = atomicAdd(&g_cursor[d], 1);
    g_elist[pos] = s;
}

// ---------------------------------------------------------------------------
// Kernel 5: gather + finalize. 16 lanes per dst node; lane owns one float4
// channel slice. out[v] = (y[v] + sum_u y[u]) / (deg+1) + b.
// ---------------------------------------------------------------------------
__global__ void __launch_bounds__(256) gather_kernel(const float* __restrict__ b,
                                                     float* __restrict__ out) {
    const int v    = blockIdx.x * (blockDim.x / 16) + (threadIdx.x >> 4);
    const int lane = threadIdx.x & 15;
    if (v >= N_NODES) return;

    const int start = g_start[v];
    const int cnt   = g_cnt[v];

    float4 acc = reinterpret_cast<const float4*>(g_y + (size_t)v * C)[lane];

    if (cnt > 0) {
        int s = g_elist[start];
        float4 u = reinterpret_cast<const float4*>(g_y + (size_t)s * C)[lane];
        for (int i = 1; i < cnt; i++) {
            int s_n = g_elist[start + i];
            float4 u_n = reinterpret_cast<const float4*>(g_y + (size_t)s_n * C)[lane];
            acc.x += u.x; acc.y += u.y; acc.z += u.z; acc.w += u.w;
            u = u_n;
        }
        acc.x += u.x; acc.y += u.y; acc.z += u.z; acc.w += u.w;
    }

    const float inv = 1.0f / (float)(cnt + 1);
    const float4 bv = reinterpret_cast<const float4*>(b)[lane];
    float4 o;
    o.x = acc.x * inv + bv.x;
    o.y = acc.y * inv + bv.y;
    o.z = acc.z * inv + bv.z;
    o.w = acc.w * inv + bv.w;
    reinterpret_cast<float4*>(out)[(size_t)v * (C / 4) + lane] = o;
}

// ---------------------------------------------------------------------------
// Launcher. Inputs (metadata order): x, edge_src, edge_dst, W_neigh, b_neigh.
// ---------------------------------------------------------------------------
extern "C" void kernel_launch(void* const* d_in, const int* in_sizes, int n_in,
                              void* d_out, int out_size) {
    const float* x   = (const float*)d_in[0];
    const void*  es  = d_in[1];
    const void*  ed  = d_in[2];
    const float* W   = (const float*)d_in[3];
    const float* b   = (const float*)d_in[4];
    float*       out = (float*)d_out;

    cudaFuncSetAttribute(gemm_wmma_kernel,
                         cudaFuncAttributeMaxDynamicSharedMemorySize, GEMM_SMEM);

    detect_kernel<<<1, 32>>>((const unsigned int*)es);

    gemm_wmma_kernel<<<N_TILES, 128, GEMM_SMEM>>>(x, W);

    hist_kernel<<<(N_EDGES + 255) / 256, 256>>>(ed);

    scan1_kernel<<<NBLK_SCAN, SCAN_BLK>>>();
    scan2_kernel<<<1, 512>>>();
    scan3_kernel<<<NBLK_SCAN, SCAN_BLK>>>();

    scatter_kernel<<<(N_EDGES + 255) / 256, 256>>>(es, ed);

    gather_kernel<<<(N_NODES * 16 + 255) / 256, 256>>>(b, out);
}